// round 12
// baseline (speedup 1.0000x reference)
#include <cuda_runtime.h>

#define NPTS 2048
// smem map (floats):
//   [0,6144)      sG   [64][3][32]        (aliased by sH [128][36]=4608 after v-pass)
//   [6144,14336)  sWb  [64][128] staged Wk then Wv  (aliased by sAx [128][34]=4352 after v-pass)
//   [14336,26624) sA2  [384][32]          (first 2304 alias sZp [8][32][9] before A2 written)
//   [26624,27904) smalls: sXr 96 | sQ 384 | sWr 128 | sWstd 384 | sZ 288
#define SMEM_FLOATS 27904
#define SMEM_BYTES (SMEM_FLOATS * 4)

// -------- scratch (device globals: allocation-free) --------
__device__ float d_We21[128 * 64];
__device__ float d_WkT[64 * 128];
__device__ float d_WvT[64 * 128];
__device__ float d_WqT[64 * 128];
__device__ float d_Wr[128];
// duplicated-pair layouts: row c has 256 floats = {w[0],w[0],w[1],w[1],...,w[127],w[127]}
// one LDG.128 per o-pair yields both FFMA2 operands pre-duplicated. +8 pad rows for prefetch.
__device__ float d_Wf1P[392 * 256];
__device__ float d_Wf2P[136 * 256];
__device__ float d_bf2s[128];
__device__ float d_q[NPTS * 384];

// -------- packed f32x2 helpers (SASS FFMA2 path, PTX-only) --------
__device__ __forceinline__ void ffma2(unsigned long long& d,
                                      unsigned long long a,
                                      unsigned long long b) {
    asm("fma.rn.f32x2 %0, %1, %2, %0;" : "+l"(d) : "l"(a), "l"(b));
}
__device__ __forceinline__ unsigned long long pack2(float x) {
    unsigned long long r;
    asm("mov.b64 %0, {%1, %1};" : "=l"(r) : "f"(x));
    return r;
}
__device__ __forceinline__ float2 unpack2(unsigned long long v) {
    float2 f;
    asm("mov.b64 {%0, %1}, %2;" : "=f"(f.x), "=f"(f.y) : "l"(v));
    return f;
}

// ---------------- prep1: We21 = We2 @ We1  (128x64) ----------------
__global__ void prep1_kernel(const float* __restrict__ We1, const float* __restrict__ We2) {
    int t = blockIdx.x, c = threadIdx.x;
    float a = 0.f;
#pragma unroll 8
    for (int e = 0; e < 128; e++) a += We2[t * 128 + e] * We1[e * 64 + c];
    d_We21[t * 64 + c] = a;
}

// ---------------- prep2: fold q/k/v + Wr + bf2 (lean, coalesced) ----------------
__global__ void prep2_kernel(const float* __restrict__ Wq, const float* __restrict__ Wk,
                             const float* __restrict__ Wv, const float* __restrict__ Wr1,
                             const float* __restrict__ Wr2, const float* __restrict__ bf2) {
    const float invS = 0.08838834764831845f;  // 1/sqrt(128)
    int o = blockIdx.x, c = threadIdx.x;
    float ak = 0.f, av = 0.f, aq = 0.f;
#pragma unroll 8
    for (int x = 0; x < 128; x++) {
        float w21 = d_We21[x * 64 + c];
        ak += Wk[o * 128 + x] * w21;
        av += Wv[o * 128 + x] * w21;
        aq += Wq[o * 128 + x] * w21;
    }
    d_WkT[c * 128 + o] = ak;
    d_WvT[c * 128 + o] = av;
    d_WqT[c * 128 + o] = aq;
    __shared__ float red[64];
    red[c] = Wr2[o * 64 + c] * Wr1[c];
    __syncthreads();
    if (c == 0) {
        float r = 0.f;
#pragma unroll
        for (int i = 0; i < 64; i++) r += red[i];
        d_Wr[o] = r;
        d_bf2s[o] = bf2[o] * invS;
    }
}

// ---------------- dup kernels: coalesced duplicated-pair weight fabrication ----------------
// block = row cc (incl. pad rows), thread = o (128). Writes 2 consecutive floats -> fully coalesced.
__global__ void dup1_kernel(const float* __restrict__ Wf1) {
    int cc = blockIdx.x;            // 0..391
    int o = threadIdx.x;            // 0..127
    float w = (cc < 384) ? Wf1[o * 384 + cc] : 0.f;
    ((float2*)(d_Wf1P + cc * 256))[o] = make_float2(w, w);
}
__global__ void dup2_kernel(const float* __restrict__ Wf2) {
    const float invS = 0.08838834764831845f;  // 1/sqrt(128)
    int cc = blockIdx.x;            // 0..135
    int o = threadIdx.x;            // 0..127
    float w = (cc < 128) ? Wf2[o * 128 + cc] * invS : 0.f;
    ((float2*)(d_Wf2P + cc * 256))[o] = make_float2(w, w);
}

// ---------------- per-point q (from s=0 column of group_fts) ----------------
__global__ void q_kernel(const float* __restrict__ gfts) {
    int p = blockIdx.x;             // b*1024 + n
    int b = p >> 10, n = p & 1023;
    int o = threadIdx.x;            // 128 threads
    const float* gbase = gfts + (size_t)b * 6291456u + (size_t)n * 32u;
    float acc0 = 0.f, acc1 = 0.f, acc2 = 0.f;
#pragma unroll 4
    for (int c = 0; c < 64; c++) {
        float w = d_WqT[c * 128 + o];
        acc0 += w * gbase[c * 98304 + 0 * 32768];
        acc1 += w * gbase[c * 98304 + 1 * 32768];
        acc2 += w * gbase[c * 98304 + 2 * 32768];
    }
    d_q[p * 384 + o * 3 + 0] = acc0;
    d_q[p * 384 + o * 3 + 1] = acc1;
    d_q[p * 384 + o * 3 + 2] = acc2;
}

// ---------------- warp reductions ----------------
__device__ __forceinline__ float wmax(float v) {
#pragma unroll
    for (int m = 16; m; m >>= 1) v = fmaxf(v, __shfl_xor_sync(0xffffffffu, v, m));
    return v;
}
__device__ __forceinline__ float wsum(float v) {
#pragma unroll
    for (int m = 16; m; m >>= 1) v += __shfl_xor_sync(0xffffffffu, v, m);
    return v;
}

// ---------------- fully fused main kernel: one CTA per point, 2 CTAs/SM ----------------
__global__ __launch_bounds__(256, 2)
void main_kernel(const float* __restrict__ gxyz, const float* __restrict__ gfts,
                 const float* __restrict__ qxyz, const float* __restrict__ Wstd,
                 const float* __restrict__ bf1, float* __restrict__ out) {
    extern __shared__ float smf[];
    float* sG    = smf;             // [64][3][32]
    float* sWb   = smf + 6144;      // [64][128]  staged Wk, then Wv
    float* sA2   = smf + 14336;     // [384][32]
    float* sZp   = smf + 14336;     // [8][32][9] alias (dead before A2 written)
    float* sH    = smf;             // [128][36]  alias sG (after v-pass)
    float* sAx   = smf + 6144;      // [128][34]  alias sWb (after v-pass); stride 34 -> 8B-aligned rows
    float* sXr   = smf + 26624;     // [3][32]
    float* sQ    = smf + 26720;     // [384]
    float* sWr   = smf + 27104;     // [128]
    float* sWstd = smf + 27232;     // [3][128]
    float* sZ    = smf + 27616;     // [9][32]

    const int p = blockIdx.x;
    const int b = p >> 10, n = p & 1023;
    const int tid = threadIdx.x;

    // ---- cooperative loads: G, Wk, smalls ----
    {
        const float4* gb4 = (const float4*)(gfts + (size_t)b * 6291456u + (size_t)n * 32u);
        for (int idx = tid; idx < 1536; idx += 256) {
            int c = idx / 24;
            int rem = idx - c * 24;
            int d = rem >> 3, s4 = rem & 7;
            ((float4*)sG)[idx] = gb4[c * 24576 + d * 8192 + s4];
        }
        for (int idx = tid; idx < 2048; idx += 256)
            ((float4*)sWb)[idx] = ((const float4*)d_WkT)[idx];
        for (int idx = tid; idx < 384; idx += 256) {
            sQ[idx] = d_q[p * 384 + idx];
            sWstd[idx] = Wstd[idx];
        }
        if (tid < 128) sWr[tid] = d_Wr[tid];
        if (tid < 96) {
            int d = tid >> 5, s = tid & 31;
            sXr[tid] = gxyz[((size_t)p * 32 + s) * 3 + d] - qxyz[(size_t)p * 3 + d];
        }
    }
    __syncthreads();

    const int s = tid & 31, r = tid >> 5, o0 = r << 4;
    const float xr0 = sXr[s], xr1 = sXr[32 + s], xr2 = sXr[64 + s];

    // ---- k-pass: k = WkT^T @ g via FFMA2 (weights from smem, broadcast) ----
    float at[16][3];
    {
        unsigned long long atp[8][3];
#pragma unroll
        for (int jp = 0; jp < 8; jp++)
#pragma unroll
            for (int d = 0; d < 3; d++) atp[jp][d] = 0ull;
#pragma unroll 2
        for (int c = 0; c < 64; c++) {
            unsigned long long g0p = pack2(sG[c * 96 + s]);
            unsigned long long g1p = pack2(sG[c * 96 + 32 + s]);
            unsigned long long g2p = pack2(sG[c * 96 + 64 + s]);
            const ulonglong2* w2 = (const ulonglong2*)(sWb + c * 128 + o0);
            ulonglong2 wa = w2[0], wb = w2[1], wc = w2[2], wd = w2[3];
            ffma2(atp[0][0], wa.x, g0p); ffma2(atp[0][1], wa.x, g1p); ffma2(atp[0][2], wa.x, g2p);
            ffma2(atp[1][0], wa.y, g0p); ffma2(atp[1][1], wa.y, g1p); ffma2(atp[1][2], wa.y, g2p);
            ffma2(atp[2][0], wb.x, g0p); ffma2(atp[2][1], wb.x, g1p); ffma2(atp[2][2], wb.x, g2p);
            ffma2(atp[3][0], wb.y, g0p); ffma2(atp[3][1], wb.y, g1p); ffma2(atp[3][2], wb.y, g2p);
            ffma2(atp[4][0], wc.x, g0p); ffma2(atp[4][1], wc.x, g1p); ffma2(atp[4][2], wc.x, g2p);
            ffma2(atp[5][0], wc.y, g0p); ffma2(atp[5][1], wc.y, g1p); ffma2(atp[5][2], wc.y, g2p);
            ffma2(atp[6][0], wd.x, g0p); ffma2(atp[6][1], wd.x, g1p); ffma2(atp[6][2], wd.x, g2p);
            ffma2(atp[7][0], wd.y, g0p); ffma2(atp[7][1], wd.y, g1p); ffma2(atp[7][2], wd.y, g2p);
        }
        // attn = q - k + pr
#pragma unroll
        for (int jp = 0; jp < 8; jp++) {
            int ia = jp * 2, ib = jp * 2 + 1;
            float wra = sWr[o0 + ia], wrb = sWr[o0 + ib];
            float2 k0 = unpack2(atp[jp][0]);
            float2 k1 = unpack2(atp[jp][1]);
            float2 k2 = unpack2(atp[jp][2]);
            at[ia][0] = sQ[(o0 + ia) * 3 + 0] - k0.x + wra * xr0;
            at[ib][0] = sQ[(o0 + ib) * 3 + 0] - k0.y + wrb * xr0;
            at[ia][1] = sQ[(o0 + ia) * 3 + 1] - k1.x + wra * xr1;
            at[ib][1] = sQ[(o0 + ib) * 3 + 1] - k1.y + wrb * xr1;
            at[ia][2] = sQ[(o0 + ia) * 3 + 2] - k2.x + wra * xr2;
            at[ib][2] = sQ[(o0 + ib) * 3 + 2] - k2.y + wrb * xr2;
        }
    }

    // ---- z0 partials (into sZp, alias of sA2 — A2 not yet written) ----
    {
        float pz[9];
#pragma unroll
        for (int jk = 0; jk < 9; jk++) pz[jk] = 0.f;
#pragma unroll
        for (int i = 0; i < 16; i++) {
            float w0 = sWstd[o0 + i];
            float w1 = sWstd[128 + o0 + i];
            float w2 = sWstd[256 + o0 + i];
#pragma unroll
            for (int k = 0; k < 3; k++) {
                float a = at[i][k];
                pz[0 * 3 + k] += w0 * a;
                pz[1 * 3 + k] += w1 * a;
                pz[2 * 3 + k] += w2 * a;
            }
        }
#pragma unroll
        for (int jk = 0; jk < 9; jk++) sZp[(r * 32 + s) * 9 + jk] = pz[jk];
    }
    __syncthreads();   // k-pass reads of sWb complete; sZp visible

    // ---- overlap: warp 0 reduces z0; everyone restages Wv into sWb ----
    for (int idx = tid; idx < 2048; idx += 256)
        ((float4*)sWb)[idx] = ((const float4*)d_WvT)[idx];
    if (r == 0) {
#pragma unroll
        for (int jk = 0; jk < 9; jk++) {
            float v = 0.f;
#pragma unroll
            for (int rr = 0; rr < 8; rr++) v += sZp[(rr * 32 + s) * 9 + jk];
            sZ[jk * 32 + s] = v;
        }
    }
    __syncthreads();

    // ---- attn2 = attn @ z0 -> sA2 (clobbers sZp, now dead) ----
    {
        float z[9];
#pragma unroll
        for (int jk = 0; jk < 9; jk++) z[jk] = sZ[jk * 32 + s];
#pragma unroll
        for (int i = 0; i < 16; i++) {
#pragma unroll
            for (int k = 0; k < 3; k++) {
                float a2 = at[i][0] * z[0 * 3 + k] + at[i][1] * z[1 * 3 + k] + at[i][2] * z[2 * 3 + k];
                sA2[((o0 + i) * 3 + k) * 32 + s] = a2;
            }
        }
    }

    // ---- v-pass: v = WvT^T @ g ; vp = v + pr stays in REGISTERS ----
    float vp[16][3];
    {
        unsigned long long vpp[8][3];
#pragma unroll
        for (int jp = 0; jp < 8; jp++)
#pragma unroll
            for (int d = 0; d < 3; d++) vpp[jp][d] = 0ull;
#pragma unroll 2
        for (int c = 0; c < 64; c++) {
            unsigned long long g0p = pack2(sG[c * 96 + s]);
            unsigned long long g1p = pack2(sG[c * 96 + 32 + s]);
            unsigned long long g2p = pack2(sG[c * 96 + 64 + s]);
            const ulonglong2* w2 = (const ulonglong2*)(sWb + c * 128 + o0);
            ulonglong2 wa = w2[0], wb = w2[1], wc = w2[2], wd = w2[3];
            ffma2(vpp[0][0], wa.x, g0p); ffma2(vpp[0][1], wa.x, g1p); ffma2(vpp[0][2], wa.x, g2p);
            ffma2(vpp[1][0], wa.y, g0p); ffma2(vpp[1][1], wa.y, g1p); ffma2(vpp[1][2], wa.y, g2p);
            ffma2(vpp[2][0], wb.x, g0p); ffma2(vpp[2][1], wb.x, g1p); ffma2(vpp[2][2], wb.x, g2p);
            ffma2(vpp[3][0], wb.y, g0p); ffma2(vpp[3][1], wb.y, g1p); ffma2(vpp[3][2], wb.y, g2p);
            ffma2(vpp[4][0], wc.x, g0p); ffma2(vpp[4][1], wc.x, g1p); ffma2(vpp[4][2], wc.x, g2p);
            ffma2(vpp[5][0], wc.y, g0p); ffma2(vpp[5][1], wc.y, g1p); ffma2(vpp[5][2], wc.y, g2p);
            ffma2(vpp[6][0], wd.x, g0p); ffma2(vpp[6][1], wd.x, g1p); ffma2(vpp[6][2], wd.x, g2p);
            ffma2(vpp[7][0], wd.y, g0p); ffma2(vpp[7][1], wd.y, g1p); ffma2(vpp[7][2], wd.y, g2p);
        }
#pragma unroll
        for (int jp = 0; jp < 8; jp++) {
            int ia = jp * 2, ib = jp * 2 + 1;
            float wra = sWr[o0 + ia], wrb = sWr[o0 + ib];
            float2 v0 = unpack2(vpp[jp][0]);
            float2 v1 = unpack2(vpp[jp][1]);
            float2 v2 = unpack2(vpp[jp][2]);
            vp[ia][0] = v0.x + wra * xr0;  vp[ib][0] = v0.y + wrb * xr0;
            vp[ia][1] = v1.x + wra * xr1;  vp[ib][1] = v1.y + wrb * xr1;
            vp[ia][2] = v2.x + wra * xr2;  vp[ib][2] = v2.y + wrb * xr2;
        }
    }
    __syncthreads();   // sA2 complete; sG/sWb dead -> sH/sAx aliases safe

    // ---- f1 GEMM (o-pair layout, dup-paired weights, 4-deep LDG prefetch) ----
    const int pr = tid & 63, sq = tid >> 6;
    {
        unsigned long long f0[4], f1a[4];
#pragma unroll
        for (int q = 0; q < 4; q++) { f0[q] = 0ull; f1a[q] = 0ull; }
        const ulonglong2* wp1 = (const ulonglong2*)d_Wf1P + pr;  // row stride 64 ull2
        ulonglong2 wbuf[4];
#pragma unroll
        for (int j = 0; j < 4; j++) wbuf[j] = __ldg(wp1 + j * 64);
        for (int cb = 0; cb < 384; cb += 4) {
#pragma unroll
            for (int j = 0; j < 4; j++) {
                ulonglong2 w = wbuf[j];
                wbuf[j] = __ldg(wp1 + (cb + 4 + j) * 64);
                const ulonglong2* av = (const ulonglong2*)(sA2 + (cb + j) * 32 + sq * 8);
                ulonglong2 a01 = av[0], a23 = av[1];
                ffma2(f0[0], a01.x, w.x); ffma2(f0[1], a01.y, w.x);
                ffma2(f0[2], a23.x, w.x); ffma2(f0[3], a23.y, w.x);
                ffma2(f1a[0], a01.x, w.y); ffma2(f1a[1], a01.y, w.y);
                ffma2(f1a[2], a23.x, w.y); ffma2(f1a[3], a23.y, w.y);
            }
        }
        float2 bb = __ldg((const float2*)bf1 + pr);
        float2* h0 = (float2*)(sH + (2 * pr) * 36 + sq * 8);
        float2* h1 = (float2*)(sH + (2 * pr + 1) * 36 + sq * 8);
#pragma unroll
        for (int q = 0; q < 4; q++) {
            float2 a = unpack2(f0[q]);
            float2 c = unpack2(f1a[q]);
            h0[q] = make_float2(fmaxf(a.x + bb.x, 0.f), fmaxf(a.y + bb.x, 0.f));
            h1[q] = make_float2(fmaxf(c.x + bb.y, 0.f), fmaxf(c.y + bb.y, 0.f));
        }
    }
    __syncthreads();

    // ---- f2 GEMM (dup-paired weights, 4-deep LDG prefetch); logits -> sAx ----
    {
        unsigned long long f0[4], f1a[4];
#pragma unroll
        for (int q = 0; q < 4; q++) { f0[q] = 0ull; f1a[q] = 0ull; }
        const ulonglong2* wp2 = (const ulonglong2*)d_Wf2P + pr;
        ulonglong2 wbuf[4];
#pragma unroll
        for (int j = 0; j < 4; j++) wbuf[j] = __ldg(wp2 + j * 64);
        for (int cb = 0; cb < 128; cb += 4) {
#pragma unroll
            for (int j = 0; j < 4; j++) {
                ulonglong2 w = wbuf[j];
                wbuf[j] = __ldg(wp2 + (cb + 4 + j) * 64);
                const ulonglong2* hv = (const ulonglong2*)(sH + (cb + j) * 36 + sq * 8);
                ulonglong2 h01 = hv[0], h23 = hv[1];
                ffma2(f0[0], h01.x, w.x); ffma2(f0[1], h01.y, w.x);
                ffma2(f0[2], h23.x, w.x); ffma2(f0[3], h23.y, w.x);
                ffma2(f1a[0], h01.x, w.y); ffma2(f1a[1], h01.y, w.y);
                ffma2(f1a[2], h23.x, w.y); ffma2(f1a[3], h23.y, w.y);
            }
        }
        float2 bb = __ldg((const float2*)d_bf2s + pr);
        float2* x0 = (float2*)(sAx + (2 * pr) * 34 + sq * 8);
        float2* x1 = (float2*)(sAx + (2 * pr + 1) * 34 + sq * 8);
#pragma unroll
        for (int q = 0; q < 4; q++) {
            float2 a = unpack2(f0[q]);
            float2 c = unpack2(f1a[q]);
            x0[q] = make_float2(a.x + bb.x, a.y + bb.x);
            x1[q] = make_float2(c.x + bb.y, c.y + bb.y);
        }
    }
    __syncthreads();

    // ---- softmax over s + weighted sum over s (vp already in regs) ----
#pragma unroll 2
    for (int i = 0; i < 16; i++) {
        int o = o0 + i;
        float x = sAx[o * 34 + s];
        float m = wmax(x);
        float e = __expf(x - m);
        float denom = wsum(e);
        float w = e / denom;
        float r0 = wsum(w * vp[i][0]);
        float r1 = wsum(w * vp[i][1]);
        float r2 = wsum(w * vp[i][2]);
        if (s == 0) {
            size_t base = (((size_t)b * 128 + o) * 3) * 1024 + n;
            out[base] = r0;
            out[base + 1024] = r1;
            out[base + 2048] = r2;
        }
    }
}

extern "C" void kernel_launch(void* const* d_in, const int* in_sizes, int n_in,
                              void* d_out, int out_size) {
    (void)in_sizes; (void)n_in; (void)out_size;
    const float* gxyz = (const float*)d_in[0];
    const float* gfts = (const float*)d_in[1];
    const float* qxyz = (const float*)d_in[2];
    cudaFuncSetAttribute(main_kernel, cudaFuncAttributeMaxDynamicSharedMemorySize, SMEM_BYTES);
    dup1_kernel<<<392, 128>>>((const float*)d_in[11]);
    dup2_kernel<<<136, 128>>>((const float*)d_in[13]);
    prep1_kernel<<<128, 64>>>((const float*)d_in[3], (const float*)d_in[4]);
    prep2_kernel<<<128, 64>>>((const float*)d_in[5],  (const float*)d_in[6],
                              (const float*)d_in[7],  (const float*)d_in[8],
                              (const float*)d_in[9],  (const float*)d_in[14]);
    q_kernel<<<NPTS, 128>>>(gfts);
    main_kernel<<<NPTS, 256, SMEM_BYTES>>>(gxyz, gfts, qxyz,
                                           (const float*)d_in[10],
                                           (const float*)d_in[12],
                                           (float*)d_out);
}

// round 14
// speedup vs baseline: 1.0465x; 1.0465x over previous
#include <cuda_runtime.h>

#define NPTS 2048
// smem map (floats):
//   [0,6144)      sG   [64][3][32]        (aliased by sH [128][36]=4608 after v-pass)
//   [6144,14336)  sWb  [64][128] staged Wk then Wv  (aliased by sAx [128][34]=4352 after v-pass)
//   [14336,26624) sA2  [384][32]          (first 2304 alias sZp [8][32][9] before A2 written)
//   [26624,27904) smalls: sXr 96 | sQ 384 | sWr 128 | sWstd 384 | sZ 288
#define SMEM_FLOATS 27904
#define SMEM_BYTES (SMEM_FLOATS * 4)

// -------- scratch (device globals: allocation-free) --------
__device__ float d_We21[128 * 64];
__device__ float d_WkT[64 * 128];
__device__ float d_WvT[64 * 128];
__device__ float d_WqT[64 * 128];
__device__ float d_Wr[128];
// duplicated-pair layouts: row c has 256 floats = {w[0],w[0],w[1],w[1],...}
// one LDG.128 per o-pair yields both FFMA2 operands pre-duplicated. +8 pad rows.
__device__ float d_Wf1P[392 * 256];
__device__ float d_Wf2P[136 * 256];
__device__ float d_bf2s[128];

// -------- packed f32x2 helpers (SASS FFMA2 path, PTX-only) --------
__device__ __forceinline__ void ffma2(unsigned long long& d,
                                      unsigned long long a,
                                      unsigned long long b) {
    asm("fma.rn.f32x2 %0, %1, %2, %0;" : "+l"(d) : "l"(a), "l"(b));
}
__device__ __forceinline__ unsigned long long pack2(float x) {
    unsigned long long r;
    asm("mov.b64 %0, {%1, %1};" : "=l"(r) : "f"(x));
    return r;
}
__device__ __forceinline__ float2 unpack2(unsigned long long v) {
    float2 f;
    asm("mov.b64 {%0, %1}, %2;" : "=f"(f.x), "=f"(f.y) : "l"(v));
    return f;
}

// ---------------- dupT: coalesced dup-pair fabrication via smem transpose ----------------
// blocks 0..5: Wf1 tiles (64 cc x 128 o); blocks 6..7: Wf2 tiles. Reads AND writes coalesced.
__global__ void dupT_kernel(const float* __restrict__ Wf1, const float* __restrict__ Wf2) {
    __shared__ float tile[64 * 129];
    const float invS = 0.08838834764831845f;  // 1/sqrt(128)
    int blk = blockIdx.x, tid = threadIdx.x;
    if (blk < 6) {
        int cc0 = blk * 64;
        for (int idx = tid; idx < 8192; idx += 256) {
            int o = idx >> 6, cc = idx & 63;
            tile[cc * 129 + o] = Wf1[o * 384 + cc0 + cc];
        }
        __syncthreads();
        for (int idx = tid; idx < 16384; idx += 256) {
            int cc = idx >> 8, j = idx & 255;
            d_Wf1P[(cc0 + cc) * 256 + j] = tile[cc * 129 + (j >> 1)];
        }
        if (blk == 5)
            for (int idx = tid; idx < 2048; idx += 256) d_Wf1P[384 * 256 + idx] = 0.f;
    } else {
        int cc0 = (blk - 6) * 64;
        for (int idx = tid; idx < 8192; idx += 256) {
            int o = idx >> 6, cc = idx & 63;
            tile[cc * 129 + o] = Wf2[o * 128 + cc0 + cc] * invS;
        }
        __syncthreads();
        for (int idx = tid; idx < 16384; idx += 256) {
            int cc = idx >> 8, j = idx & 255;
            d_Wf2P[(cc0 + cc) * 256 + j] = tile[cc * 129 + (j >> 1)];
        }
        if (blk == 7)
            for (int idx = tid; idx < 2048; idx += 256) d_Wf2P[128 * 256 + idx] = 0.f;
    }
}

// ---------------- prep1: We21 = We2 @ We1 (128x64), 256-thread split-e ----------------
__global__ void prep1_kernel(const float* __restrict__ We1, const float* __restrict__ We2) {
    __shared__ float red[256];
    int t = blockIdx.x, tid = threadIdx.x;
    int c = tid & 63, eq = tid >> 6;
    float a = 0.f;
#pragma unroll 8
    for (int e = eq * 32; e < eq * 32 + 32; e++)
        a += We2[t * 128 + e] * We1[e * 64 + c];
    red[tid] = a;
    __syncthreads();
    if (tid < 64)
        d_We21[t * 64 + tid] = red[tid] + red[64 + tid] + red[128 + tid] + red[192 + tid];
}

// ---------------- prep2: fold q/k/v + Wr + bf2, 256-thread split-x ----------------
__global__ void prep2_kernel(const float* __restrict__ Wq, const float* __restrict__ Wk,
                             const float* __restrict__ Wv, const float* __restrict__ Wr1,
                             const float* __restrict__ Wr2, const float* __restrict__ bf2) {
    __shared__ float red[768];
    __shared__ float redr[64];
    const float invS = 0.08838834764831845f;  // 1/sqrt(128)
    int o = blockIdx.x, tid = threadIdx.x;
    int c = tid & 63, xq = tid >> 6;
    float ak = 0.f, av = 0.f, aq = 0.f;
#pragma unroll 8
    for (int x = xq * 32; x < xq * 32 + 32; x++) {
        float w21 = d_We21[x * 64 + c];
        ak += Wk[o * 128 + x] * w21;
        av += Wv[o * 128 + x] * w21;
        aq += Wq[o * 128 + x] * w21;
    }
    red[tid] = ak; red[256 + tid] = av; red[512 + tid] = aq;
    if (tid < 64) redr[tid] = Wr2[o * 64 + tid] * Wr1[tid];
    __syncthreads();
    if (tid < 64) {
        float sk = red[tid] + red[64 + tid] + red[128 + tid] + red[192 + tid];
        float sv = red[256 + tid] + red[320 + tid] + red[384 + tid] + red[448 + tid];
        float sq = red[512 + tid] + red[576 + tid] + red[640 + tid] + red[704 + tid];
        d_WkT[tid * 128 + o] = sk;
        d_WvT[tid * 128 + o] = sv;
        d_WqT[tid * 128 + o] = sq;
    } else if (tid == 64) {
        float r = 0.f;
#pragma unroll
        for (int i = 0; i < 64; i++) r += redr[i];
        d_Wr[o] = r;
        d_bf2s[o] = bf2[o] * invS;
    }
}

// ---------------- warp reductions ----------------
__device__ __forceinline__ float wmax(float v) {
#pragma unroll
    for (int m = 16; m; m >>= 1) v = fmaxf(v, __shfl_xor_sync(0xffffffffu, v, m));
    return v;
}
__device__ __forceinline__ float wsum(float v) {
#pragma unroll
    for (int m = 16; m; m >>= 1) v += __shfl_xor_sync(0xffffffffu, v, m);
    return v;
}

// ---------------- fully fused main kernel: one CTA per point, 2 CTAs/SM ----------------
__global__ __launch_bounds__(256, 2)
void main_kernel(const float* __restrict__ gxyz, const float* __restrict__ gfts,
                 const float* __restrict__ qxyz, const float* __restrict__ Wstd,
                 const float* __restrict__ bf1, float* __restrict__ out) {
    extern __shared__ float smf[];
    float* sG    = smf;             // [64][3][32]
    float* sWb   = smf + 6144;      // [64][128]  staged Wk, then Wv
    float* sA2   = smf + 14336;     // [384][32]
    float* sZp   = smf + 14336;     // [8][32][9] alias (dead before A2 written)
    float* sH    = smf;             // [128][36]  alias sG (after v-pass)
    float* sAx   = smf + 6144;      // [128][34]  alias sWb (after v-pass)
    float* sXr   = smf + 26624;     // [3][32]
    float* sQ    = smf + 26720;     // [384]
    float* sWr   = smf + 27104;     // [128]
    float* sWstd = smf + 27232;     // [3][128]
    float* sZ    = smf + 27616;     // [9][32]

    const int p = blockIdx.x;
    const int b = p >> 10, n = p & 1023;
    const int tid = threadIdx.x;

    // ---- cooperative loads: G, Wk, smalls ----
    {
        const float4* gb4 = (const float4*)(gfts + (size_t)b * 6291456u + (size_t)n * 32u);
        for (int idx = tid; idx < 1536; idx += 256) {
            int c = idx / 24;
            int rem = idx - c * 24;
            int d = rem >> 3, s4 = rem & 7;
            ((float4*)sG)[idx] = gb4[c * 24576 + d * 8192 + s4];
        }
        for (int idx = tid; idx < 2048; idx += 256)
            ((float4*)sWb)[idx] = ((const float4*)d_WkT)[idx];
        for (int idx = tid; idx < 384; idx += 256)
            sWstd[idx] = Wstd[idx];
        if (tid < 128) sWr[tid] = d_Wr[tid];
        if (tid < 96) {
            int d = tid >> 5, s = tid & 31;
            sXr[tid] = gxyz[((size_t)p * 32 + s) * 3 + d] - qxyz[(size_t)p * 3 + d];
        }
    }
    __syncthreads();

    // ---- q inline: q[o][d] = sum_c WqT[c][o] * G[c][d][0] ----
    {
        int o = tid & 127;
        const float* wq = d_WqT + o;
        if (tid < 128) {
            float a0 = 0.f, a2 = 0.f;
#pragma unroll 8
            for (int c = 0; c < 64; c++) {
                float w = wq[c * 128];
                a0 += w * sG[c * 96];
                a2 += w * sG[c * 96 + 64];
            }
            sQ[o * 3 + 0] = a0;
            sQ[o * 3 + 2] = a2;
        } else {
            float a1 = 0.f;
#pragma unroll 8
            for (int c = 0; c < 64; c++)
                a1 += wq[c * 128] * sG[c * 96 + 32];
            sQ[o * 3 + 1] = a1;
        }
    }
    __syncthreads();

    const int s = tid & 31, r = tid >> 5, o0 = r << 4;
    const float xr0 = sXr[s], xr1 = sXr[32 + s], xr2 = sXr[64 + s];

    // ---- k-pass: k = WkT^T @ g via FFMA2 (weights from smem, broadcast) ----
    float at[16][3];
    {
        unsigned long long atp[8][3];
#pragma unroll
        for (int jp = 0; jp < 8; jp++)
#pragma unroll
            for (int d = 0; d < 3; d++) atp[jp][d] = 0ull;
#pragma unroll 2
        for (int c = 0; c < 64; c++) {
            unsigned long long g0p = pack2(sG[c * 96 + s]);
            unsigned long long g1p = pack2(sG[c * 96 + 32 + s]);
            unsigned long long g2p = pack2(sG[c * 96 + 64 + s]);
            const ulonglong2* w2 = (const ulonglong2*)(sWb + c * 128 + o0);
            ulonglong2 wa = w2[0], wb = w2[1], wc = w2[2], wd = w2[3];
            ffma2(atp[0][0], wa.x, g0p); ffma2(atp[0][1], wa.x, g1p); ffma2(atp[0][2], wa.x, g2p);
            ffma2(atp[1][0], wa.y, g0p); ffma2(atp[1][1], wa.y, g1p); ffma2(atp[1][2], wa.y, g2p);
            ffma2(atp[2][0], wb.x, g0p); ffma2(atp[2][1], wb.x, g1p); ffma2(atp[2][2], wb.x, g2p);
            ffma2(atp[3][0], wb.y, g0p); ffma2(atp[3][1], wb.y, g1p); ffma2(atp[3][2], wb.y, g2p);
            ffma2(atp[4][0], wc.x, g0p); ffma2(atp[4][1], wc.x, g1p); ffma2(atp[4][2], wc.x, g2p);
            ffma2(atp[5][0], wc.y, g0p); ffma2(atp[5][1], wc.y, g1p); ffma2(atp[5][2], wc.y, g2p);
            ffma2(atp[6][0], wd.x, g0p); ffma2(atp[6][1], wd.x, g1p); ffma2(atp[6][2], wd.x, g2p);
            ffma2(atp[7][0], wd.y, g0p); ffma2(atp[7][1], wd.y, g1p); ffma2(atp[7][2], wd.y, g2p);
        }
        // attn = q - k + pr
#pragma unroll
        for (int jp = 0; jp < 8; jp++) {
            int ia = jp * 2, ib = jp * 2 + 1;
            float wra = sWr[o0 + ia], wrb = sWr[o0 + ib];
            float2 k0 = unpack2(atp[jp][0]);
            float2 k1 = unpack2(atp[jp][1]);
            float2 k2 = unpack2(atp[jp][2]);
            at[ia][0] = sQ[(o0 + ia) * 3 + 0] - k0.x + wra * xr0;
            at[ib][0] = sQ[(o0 + ib) * 3 + 0] - k0.y + wrb * xr0;
            at[ia][1] = sQ[(o0 + ia) * 3 + 1] - k1.x + wra * xr1;
            at[ib][1] = sQ[(o0 + ib) * 3 + 1] - k1.y + wrb * xr1;
            at[ia][2] = sQ[(o0 + ia) * 3 + 2] - k2.x + wra * xr2;
            at[ib][2] = sQ[(o0 + ib) * 3 + 2] - k2.y + wrb * xr2;
        }
    }

    // ---- z0 partials (into sZp, alias of sA2 — A2 not yet written) ----
    {
        float pz[9];
#pragma unroll
        for (int jk = 0; jk < 9; jk++) pz[jk] = 0.f;
#pragma unroll
        for (int i = 0; i < 16; i++) {
            float w0 = sWstd[o0 + i];
            float w1 = sWstd[128 + o0 + i];
            float w2 = sWstd[256 + o0 + i];
#pragma unroll
            for (int k = 0; k < 3; k++) {
                float a = at[i][k];
                pz[0 * 3 + k] += w0 * a;
                pz[1 * 3 + k] += w1 * a;
                pz[2 * 3 + k] += w2 * a;
            }
        }
#pragma unroll
        for (int jk = 0; jk < 9; jk++) sZp[(r * 32 + s) * 9 + jk] = pz[jk];
    }
    __syncthreads();   // k-pass reads of sWb complete; sZp visible

    // ---- overlap: warp 0 reduces z0; everyone restages Wv into sWb ----
    for (int idx = tid; idx < 2048; idx += 256)
        ((float4*)sWb)[idx] = ((const float4*)d_WvT)[idx];
    if (r == 0) {
#pragma unroll
        for (int jk = 0; jk < 9; jk++) {
            float v = 0.f;
#pragma unroll
            for (int rr = 0; rr < 8; rr++) v += sZp[(rr * 32 + s) * 9 + jk];
            sZ[jk * 32 + s] = v;
        }
    }
    __syncthreads();

    // ---- attn2 = attn @ z0 -> sA2 (clobbers sZp, now dead) ----
    {
        float z[9];
#pragma unroll
        for (int jk = 0; jk < 9; jk++) z[jk] = sZ[jk * 32 + s];
#pragma unroll
        for (int i = 0; i < 16; i++) {
#pragma unroll
            for (int k = 0; k < 3; k++) {
                float a2 = at[i][0] * z[0 * 3 + k] + at[i][1] * z[1 * 3 + k] + at[i][2] * z[2 * 3 + k];
                sA2[((o0 + i) * 3 + k) * 32 + s] = a2;
            }
        }
    }

    // ---- v-pass: v = WvT^T @ g ; vp = v + pr stays in REGISTERS ----
    float vp[16][3];
    {
        unsigned long long vpp[8][3];
#pragma unroll
        for (int jp = 0; jp < 8; jp++)
#pragma unroll
            for (int d = 0; d < 3; d++) vpp[jp][d] = 0ull;
#pragma unroll 2
        for (int c = 0; c < 64; c++) {
            unsigned long long g0p = pack2(sG[c * 96 + s]);
            unsigned long long g1p = pack2(sG[c * 96 + 32 + s]);
            unsigned long long g2p = pack2(sG[c * 96 + 64 + s]);
            const ulonglong2* w2 = (const ulonglong2*)(sWb + c * 128 + o0);
            ulonglong2 wa = w2[0], wb = w2[1], wc = w2[2], wd = w2[3];
            ffma2(vpp[0][0], wa.x, g0p); ffma2(vpp[0][1], wa.x, g1p); ffma2(vpp[0][2], wa.x, g2p);
            ffma2(vpp[1][0], wa.y, g0p); ffma2(vpp[1][1], wa.y, g1p); ffma2(vpp[1][2], wa.y, g2p);
            ffma2(vpp[2][0], wb.x, g0p); ffma2(vpp[2][1], wb.x, g1p); ffma2(vpp[2][2], wb.x, g2p);
            ffma2(vpp[3][0], wb.y, g0p); ffma2(vpp[3][1], wb.y, g1p); ffma2(vpp[3][2], wb.y, g2p);
            ffma2(vpp[4][0], wc.x, g0p); ffma2(vpp[4][1], wc.x, g1p); ffma2(vpp[4][2], wc.x, g2p);
            ffma2(vpp[5][0], wc.y, g0p); ffma2(vpp[5][1], wc.y, g1p); ffma2(vpp[5][2], wc.y, g2p);
            ffma2(vpp[6][0], wd.x, g0p); ffma2(vpp[6][1], wd.x, g1p); ffma2(vpp[6][2], wd.x, g2p);
            ffma2(vpp[7][0], wd.y, g0p); ffma2(vpp[7][1], wd.y, g1p); ffma2(vpp[7][2], wd.y, g2p);
        }
#pragma unroll
        for (int jp = 0; jp < 8; jp++) {
            int ia = jp * 2, ib = jp * 2 + 1;
            float wra = sWr[o0 + ia], wrb = sWr[o0 + ib];
            float2 v0 = unpack2(vpp[jp][0]);
            float2 v1 = unpack2(vpp[jp][1]);
            float2 v2 = unpack2(vpp[jp][2]);
            vp[ia][0] = v0.x + wra * xr0;  vp[ib][0] = v0.y + wrb * xr0;
            vp[ia][1] = v1.x + wra * xr1;  vp[ib][1] = v1.y + wrb * xr1;
            vp[ia][2] = v2.x + wra * xr2;  vp[ib][2] = v2.y + wrb * xr2;
        }
    }
    __syncthreads();   // sA2 complete; sG/sWb dead -> sH/sAx aliases safe

    // ---- f1 GEMM (o-pair layout, dup-paired weights, 4-deep LDG prefetch) ----
    const int pr = tid & 63, sq = tid >> 6;
    {
        unsigned long long f0[4], f1a[4];
#pragma unroll
        for (int q = 0; q < 4; q++) { f0[q] = 0ull; f1a[q] = 0ull; }
        const ulonglong2* wp1 = (const ulonglong2*)d_Wf1P + pr;  // row stride 64 ull2
        ulonglong2 wbuf[4];
#pragma unroll
        for (int j = 0; j < 4; j++) wbuf[j] = __ldg(wp1 + j * 64);
        for (int cb = 0; cb < 384; cb += 4) {
#pragma unroll
            for (int j = 0; j < 4; j++) {
                ulonglong2 w = wbuf[j];
                wbuf[j] = __ldg(wp1 + (cb + 4 + j) * 64);
                const ulonglong2* av = (const ulonglong2*)(sA2 + (cb + j) * 32 + sq * 8);
                ulonglong2 a01 = av[0], a23 = av[1];
                ffma2(f0[0], a01.x, w.x); ffma2(f0[1], a01.y, w.x);
                ffma2(f0[2], a23.x, w.x); ffma2(f0[3], a23.y, w.x);
                ffma2(f1a[0], a01.x, w.y); ffma2(f1a[1], a01.y, w.y);
                ffma2(f1a[2], a23.x, w.y); ffma2(f1a[3], a23.y, w.y);
            }
        }
        float2 bb = __ldg((const float2*)bf1 + pr);
        float2* h0 = (float2*)(sH + (2 * pr) * 36 + sq * 8);
        float2* h1 = (float2*)(sH + (2 * pr + 1) * 36 + sq * 8);
#pragma unroll
        for (int q = 0; q < 4; q++) {
            float2 a = unpack2(f0[q]);
            float2 c = unpack2(f1a[q]);
            h0[q] = make_float2(fmaxf(a.x + bb.x, 0.f), fmaxf(a.y + bb.x, 0.f));
            h1[q] = make_float2(fmaxf(c.x + bb.y, 0.f), fmaxf(c.y + bb.y, 0.f));
        }
    }
    __syncthreads();

    // ---- f2 GEMM (dup-paired weights, 4-deep LDG prefetch); logits -> sAx ----
    {
        unsigned long long f0[4], f1a[4];
#pragma unroll
        for (int q = 0; q < 4; q++) { f0[q] = 0ull; f1a[q] = 0ull; }
        const ulonglong2* wp2 = (const ulonglong2*)d_Wf2P + pr;
        ulonglong2 wbuf[4];
#pragma unroll
        for (int j = 0; j < 4; j++) wbuf[j] = __ldg(wp2 + j * 64);
        for (int cb = 0; cb < 128; cb += 4) {
#pragma unroll
            for (int j = 0; j < 4; j++) {
                ulonglong2 w = wbuf[j];
                wbuf[j] = __ldg(wp2 + (cb + 4 + j) * 64);
                const ulonglong2* hv = (const ulonglong2*)(sH + (cb + j) * 36 + sq * 8);
                ulonglong2 h01 = hv[0], h23 = hv[1];
                ffma2(f0[0], h01.x, w.x); ffma2(f0[1], h01.y, w.x);
                ffma2(f0[2], h23.x, w.x); ffma2(f0[3], h23.y, w.x);
                ffma2(f1a[0], h01.x, w.y); ffma2(f1a[1], h01.y, w.y);
                ffma2(f1a[2], h23.x, w.y); ffma2(f1a[3], h23.y, w.y);
            }
        }
        float2 bb = __ldg((const float2*)d_bf2s + pr);
        float2* x0 = (float2*)(sAx + (2 * pr) * 34 + sq * 8);
        float2* x1 = (float2*)(sAx + (2 * pr + 1) * 34 + sq * 8);
#pragma unroll
        for (int q = 0; q < 4; q++) {
            float2 a = unpack2(f0[q]);
            float2 c = unpack2(f1a[q]);
            x0[q] = make_float2(a.x + bb.x, a.y + bb.x);
            x1[q] = make_float2(c.x + bb.y, c.y + bb.y);
        }
    }
    __syncthreads();

    // ---- softmax over s + weighted sum over s (vp already in regs) ----
#pragma unroll 2
    for (int i = 0; i < 16; i++) {
        int o = o0 + i;
        float x = sAx[o * 34 + s];
        float m = wmax(x);
        float e = __expf(x - m);
        float denom = wsum(e);
        float w = e / denom;
        float r0 = wsum(w * vp[i][0]);
        float r1 = wsum(w * vp[i][1]);
        float r2 = wsum(w * vp[i][2]);
        if (s == 0) {
            size_t base = (((size_t)b * 128 + o) * 3) * 1024 + n;
            out[base] = r0;
            out[base + 1024] = r1;
            out[base + 2048] = r2;
        }
    }
}

extern "C" void kernel_launch(void* const* d_in, const int* in_sizes, int n_in,
                              void* d_out, int out_size) {
    (void)in_sizes; (void)n_in; (void)out_size;
    const float* gxyz = (const float*)d_in[0];
    const float* gfts = (const float*)d_in[1];
    const float* qxyz = (const float*)d_in[2];
    cudaFuncSetAttribute(main_kernel, cudaFuncAttributeMaxDynamicSharedMemorySize, SMEM_BYTES);
    dupT_kernel<<<8, 256>>>((const float*)d_in[11], (const float*)d_in[13]);
    prep1_kernel<<<128, 256>>>((const float*)d_in[3], (const float*)d_in[4]);
    prep2_kernel<<<128, 256>>>((const float*)d_in[5], (const float*)d_in[6],
                               (const float*)d_in[7], (const float*)d_in[8],
                               (const float*)d_in[9], (const float*)d_in[14]);
    main_kernel<<<NPTS, 256, SMEM_BYTES>>>(gxyz, gfts, qxyz,
                                           (const float*)d_in[10],
                                           (const float*)d_in[12],
                                           (float*)d_out);
}

// round 15
// speedup vs baseline: 1.1620x; 1.1104x over previous
#include <cuda_runtime.h>

#define NPTS 2048
// smem map (floats):
//   [0,6144)      sG   [64][3][32]        (aliased by sH [128][36]=4608 after v-pass)
//   [6144,14336)  sWb  [64][128] staged Wk then Wv  (aliased by sAx [128][34]=4352 after v-pass)
//   [14336,26720) sA2  [384][32]=12288    (first 2304 alias sZp; whole region re-aliased by
//                                          sVp [3][32][129]=12384 after f1)
//   [26720,28000) smalls: sXr 96 | sQ 384 | sWr 128 | sWstd 384 | sZ 288
#define SMEM_FLOATS 28000
#define SMEM_BYTES (SMEM_FLOATS * 4)

// -------- scratch (device globals: allocation-free) --------
__device__ float d_We21[128 * 64];
__device__ float d_WkT[64 * 128];
__device__ float d_WvT[64 * 128];
__device__ float d_WqT[64 * 128];
__device__ float d_Wr[128];
// duplicated-pair layouts: row c has 256 floats = {w[0],w[0],w[1],w[1],...}
__device__ float d_Wf1P[392 * 256];
__device__ float d_Wf2P[136 * 256];
__device__ float d_bf2s[128];

// -------- packed f32x2 helpers (SASS FFMA2 path, PTX-only) --------
__device__ __forceinline__ void ffma2(unsigned long long& d,
                                      unsigned long long a,
                                      unsigned long long b) {
    asm("fma.rn.f32x2 %0, %1, %2, %0;" : "+l"(d) : "l"(a), "l"(b));
}
__device__ __forceinline__ unsigned long long pack2(float x) {
    unsigned long long r;
    asm("mov.b64 %0, {%1, %1};" : "=l"(r) : "f"(x));
    return r;
}
__device__ __forceinline__ float2 unpack2(unsigned long long v) {
    float2 f;
    asm("mov.b64 {%0, %1}, %2;" : "=f"(f.x), "=f"(f.y) : "l"(v));
    return f;
}

// ---------------- dupT: coalesced dup-pair fabrication via smem transpose ----------------
__global__ void dupT_kernel(const float* __restrict__ Wf1, const float* __restrict__ Wf2) {
    __shared__ float tile[64 * 129];
    const float invS = 0.08838834764831845f;  // 1/sqrt(128)
    int blk = blockIdx.x, tid = threadIdx.x;
    if (blk < 6) {
        int cc0 = blk * 64;
        for (int idx = tid; idx < 8192; idx += 256) {
            int o = idx >> 6, cc = idx & 63;
            tile[cc * 129 + o] = Wf1[o * 384 + cc0 + cc];
        }
        __syncthreads();
        for (int idx = tid; idx < 16384; idx += 256) {
            int cc = idx >> 8, j = idx & 255;
            d_Wf1P[(cc0 + cc) * 256 + j] = tile[cc * 129 + (j >> 1)];
        }
        if (blk == 5)
            for (int idx = tid; idx < 2048; idx += 256) d_Wf1P[384 * 256 + idx] = 0.f;
    } else {
        int cc0 = (blk - 6) * 64;
        for (int idx = tid; idx < 8192; idx += 256) {
            int o = idx >> 6, cc = idx & 63;
            tile[cc * 129 + o] = Wf2[o * 128 + cc0 + cc] * invS;
        }
        __syncthreads();
        for (int idx = tid; idx < 16384; idx += 256) {
            int cc = idx >> 8, j = idx & 255;
            d_Wf2P[(cc0 + cc) * 256 + j] = tile[cc * 129 + (j >> 1)];
        }
        if (blk == 7)
            for (int idx = tid; idx < 2048; idx += 256) d_Wf2P[128 * 256 + idx] = 0.f;
    }
}

// ---------------- prep1: We21 = We2 @ We1 (128x64), 256-thread split-e ----------------
__global__ void prep1_kernel(const float* __restrict__ We1, const float* __restrict__ We2) {
    __shared__ float red[256];
    int t = blockIdx.x, tid = threadIdx.x;
    int c = tid & 63, eq = tid >> 6;
    float a = 0.f;
#pragma unroll 8
    for (int e = eq * 32; e < eq * 32 + 32; e++)
        a += We2[t * 128 + e] * We1[e * 64 + c];
    red[tid] = a;
    __syncthreads();
    if (tid < 64)
        d_We21[t * 64 + tid] = red[tid] + red[64 + tid] + red[128 + tid] + red[192 + tid];
}

// ---------------- prep2: fold q/k/v + Wr + bf2, 256-thread split-x ----------------
__global__ void prep2_kernel(const float* __restrict__ Wq, const float* __restrict__ Wk,
                             const float* __restrict__ Wv, const float* __restrict__ Wr1,
                             const float* __restrict__ Wr2, const float* __restrict__ bf2) {
    __shared__ float red[768];
    __shared__ float redr[64];
    const float invS = 0.08838834764831845f;  // 1/sqrt(128)
    int o = blockIdx.x, tid = threadIdx.x;
    int c = tid & 63, xq = tid >> 6;
    float ak = 0.f, av = 0.f, aq = 0.f;
#pragma unroll 8
    for (int x = xq * 32; x < xq * 32 + 32; x++) {
        float w21 = d_We21[x * 64 + c];
        ak += Wk[o * 128 + x] * w21;
        av += Wv[o * 128 + x] * w21;
        aq += Wq[o * 128 + x] * w21;
    }
    red[tid] = ak; red[256 + tid] = av; red[512 + tid] = aq;
    if (tid < 64) redr[tid] = Wr2[o * 64 + tid] * Wr1[tid];
    __syncthreads();
    if (tid < 64) {
        float sk = red[tid] + red[64 + tid] + red[128 + tid] + red[192 + tid];
        float sv = red[256 + tid] + red[320 + tid] + red[384 + tid] + red[448 + tid];
        float sq = red[512 + tid] + red[576 + tid] + red[640 + tid] + red[704 + tid];
        d_WkT[tid * 128 + o] = sk;
        d_WvT[tid * 128 + o] = sv;
        d_WqT[tid * 128 + o] = sq;
    } else if (tid == 64) {
        float r = 0.f;
#pragma unroll
        for (int i = 0; i < 64; i++) r += redr[i];
        d_Wr[o] = r;
        d_bf2s[o] = bf2[o] * invS;
    }
}

// ---------------- fully fused main kernel: one CTA per point, 2 CTAs/SM ----------------
__global__ __launch_bounds__(256, 2)
void main_kernel(const float* __restrict__ gxyz, const float* __restrict__ gfts,
                 const float* __restrict__ qxyz, const float* __restrict__ Wstd,
                 const float* __restrict__ bf1, float* __restrict__ out) {
    extern __shared__ float smf[];
    float* sG    = smf;             // [64][3][32]
    float* sWb   = smf + 6144;      // [64][128]  staged Wk, then Wv
    float* sA2   = smf + 14336;     // [384][32]
    float* sZp   = smf + 14336;     // [8][32][9] alias (dead before A2 written)
    float* sVp   = smf + 14336;     // [3][32][129] alias of sA2 (after f1)
    float* sH    = smf;             // [128][36]  alias sG (after v-pass)
    float* sAx   = smf + 6144;      // [128][34]  alias sWb (after v-pass)
    float* sXr   = smf + 26720;     // [3][32]
    float* sQ    = smf + 26816;     // [384]
    float* sWr   = smf + 27200;     // [128]
    float* sWstd = smf + 27328;     // [3][128]
    float* sZ    = smf + 27712;     // [9][32]

    const int p = blockIdx.x;
    const int b = p >> 10, n = p & 1023;
    const int tid = threadIdx.x;

    // ---- cooperative loads: G, Wk, smalls ----
    {
        const float4* gb4 = (const float4*)(gfts + (size_t)b * 6291456u + (size_t)n * 32u);
        for (int idx = tid; idx < 1536; idx += 256) {
            int c = idx / 24;
            int rem = idx - c * 24;
            int d = rem >> 3, s4 = rem & 7;
            ((float4*)sG)[idx] = gb4[c * 24576 + d * 8192 + s4];
        }
        for (int idx = tid; idx < 2048; idx += 256)
            ((float4*)sWb)[idx] = ((const float4*)d_WkT)[idx];
        for (int idx = tid; idx < 384; idx += 256)
            sWstd[idx] = Wstd[idx];
        if (tid < 128) sWr[tid] = d_Wr[tid];
        if (tid < 96) {
            int d = tid >> 5, s = tid & 31;
            sXr[tid] = gxyz[((size_t)p * 32 + s) * 3 + d] - qxyz[(size_t)p * 3 + d];
        }
    }
    __syncthreads();

    // ---- q inline: q[o][d] = sum_c WqT[c][o] * G[c][d][0] ----
    {
        int o = tid & 127;
        const float* wq = d_WqT + o;
        if (tid < 128) {
            float a0 = 0.f, a2 = 0.f;
#pragma unroll 8
            for (int c = 0; c < 64; c++) {
                float w = wq[c * 128];
                a0 += w * sG[c * 96];
                a2 += w * sG[c * 96 + 64];
            }
            sQ[o * 3 + 0] = a0;
            sQ[o * 3 + 2] = a2;
        } else {
            float a1 = 0.f;
#pragma unroll 8
            for (int c = 0; c < 64; c++)
                a1 += wq[c * 128] * sG[c * 96 + 32];
            sQ[o * 3 + 1] = a1;
        }
    }
    __syncthreads();

    const int s = tid & 31, r = tid >> 5, o0 = r << 4;
    const float xr0 = sXr[s], xr1 = sXr[32 + s], xr2 = sXr[64 + s];

    // ---- k-pass: k = WkT^T @ g via FFMA2 (weights from smem, broadcast) ----
    float at[16][3];
    {
        unsigned long long atp[8][3];
#pragma unroll
        for (int jp = 0; jp < 8; jp++)
#pragma unroll
            for (int d = 0; d < 3; d++) atp[jp][d] = 0ull;
#pragma unroll 2
        for (int c = 0; c < 64; c++) {
            unsigned long long g0p = pack2(sG[c * 96 + s]);
            unsigned long long g1p = pack2(sG[c * 96 + 32 + s]);
            unsigned long long g2p = pack2(sG[c * 96 + 64 + s]);
            const ulonglong2* w2 = (const ulonglong2*)(sWb + c * 128 + o0);
            ulonglong2 wa = w2[0], wb = w2[1], wc = w2[2], wd = w2[3];
            ffma2(atp[0][0], wa.x, g0p); ffma2(atp[0][1], wa.x, g1p); ffma2(atp[0][2], wa.x, g2p);
            ffma2(atp[1][0], wa.y, g0p); ffma2(atp[1][1], wa.y, g1p); ffma2(atp[1][2], wa.y, g2p);
            ffma2(atp[2][0], wb.x, g0p); ffma2(atp[2][1], wb.x, g1p); ffma2(atp[2][2], wb.x, g2p);
            ffma2(atp[3][0], wb.y, g0p); ffma2(atp[3][1], wb.y, g1p); ffma2(atp[3][2], wb.y, g2p);
            ffma2(atp[4][0], wc.x, g0p); ffma2(atp[4][1], wc.x, g1p); ffma2(atp[4][2], wc.x, g2p);
            ffma2(atp[5][0], wc.y, g0p); ffma2(atp[5][1], wc.y, g1p); ffma2(atp[5][2], wc.y, g2p);
            ffma2(atp[6][0], wd.x, g0p); ffma2(atp[6][1], wd.x, g1p); ffma2(atp[6][2], wd.x, g2p);
            ffma2(atp[7][0], wd.y, g0p); ffma2(atp[7][1], wd.y, g1p); ffma2(atp[7][2], wd.y, g2p);
        }
        // attn = q - k + pr
#pragma unroll
        for (int jp = 0; jp < 8; jp++) {
            int ia = jp * 2, ib = jp * 2 + 1;
            float wra = sWr[o0 + ia], wrb = sWr[o0 + ib];
            float2 k0 = unpack2(atp[jp][0]);
            float2 k1 = unpack2(atp[jp][1]);
            float2 k2 = unpack2(atp[jp][2]);
            at[ia][0] = sQ[(o0 + ia) * 3 + 0] - k0.x + wra * xr0;
            at[ib][0] = sQ[(o0 + ib) * 3 + 0] - k0.y + wrb * xr0;
            at[ia][1] = sQ[(o0 + ia) * 3 + 1] - k1.x + wra * xr1;
            at[ib][1] = sQ[(o0 + ib) * 3 + 1] - k1.y + wrb * xr1;
            at[ia][2] = sQ[(o0 + ia) * 3 + 2] - k2.x + wra * xr2;
            at[ib][2] = sQ[(o0 + ib) * 3 + 2] - k2.y + wrb * xr2;
        }
    }

    // ---- z0 partials (into sZp, alias of sA2 — A2 not yet written) ----
    {
        float pz[9];
#pragma unroll
        for (int jk = 0; jk < 9; jk++) pz[jk] = 0.f;
#pragma unroll
        for (int i = 0; i < 16; i++) {
            float w0 = sWstd[o0 + i];
            float w1 = sWstd[128 + o0 + i];
            float w2 = sWstd[256 + o0 + i];
#pragma unroll
            for (int k = 0; k < 3; k++) {
                float a = at[i][k];
                pz[0 * 3 + k] += w0 * a;
                pz[1 * 3 + k] += w1 * a;
                pz[2 * 3 + k] += w2 * a;
            }
        }
#pragma unroll
        for (int jk = 0; jk < 9; jk++) sZp[(r * 32 + s) * 9 + jk] = pz[jk];
    }
    __syncthreads();   // k-pass reads of sWb complete; sZp visible

    // ---- overlap: warp 0 reduces z0; everyone restages Wv into sWb ----
    for (int idx = tid; idx < 2048; idx += 256)
        ((float4*)sWb)[idx] = ((const float4*)d_WvT)[idx];
    if (r == 0) {
#pragma unroll
        for (int jk = 0; jk < 9; jk++) {
            float v = 0.f;
#pragma unroll
            for (int rr = 0; rr < 8; rr++) v += sZp[(rr * 32 + s) * 9 + jk];
            sZ[jk * 32 + s] = v;
        }
    }
    __syncthreads();

    // ---- attn2 = attn @ z0 -> sA2 (clobbers sZp, now dead) ----
    {
        float z[9];
#pragma unroll
        for (int jk = 0; jk < 9; jk++) z[jk] = sZ[jk * 32 + s];
#pragma unroll
        for (int i = 0; i < 16; i++) {
#pragma unroll
            for (int k = 0; k < 3; k++) {
                float a2 = at[i][0] * z[0 * 3 + k] + at[i][1] * z[1 * 3 + k] + at[i][2] * z[2 * 3 + k];
                sA2[((o0 + i) * 3 + k) * 32 + s] = a2;
            }
        }
    }

    // ---- v-pass: v = WvT^T @ g ; vp = v + pr stays in REGISTERS (until after f1) ----
    float vp[16][3];
    {
        unsigned long long vpp[8][3];
#pragma unroll
        for (int jp = 0; jp < 8; jp++)
#pragma unroll
            for (int d = 0; d < 3; d++) vpp[jp][d] = 0ull;
#pragma unroll 2
        for (int c = 0; c < 64; c++) {
            unsigned long long g0p = pack2(sG[c * 96 + s]);
            unsigned long long g1p = pack2(sG[c * 96 + 32 + s]);
            unsigned long long g2p = pack2(sG[c * 96 + 64 + s]);
            const ulonglong2* w2 = (const ulonglong2*)(sWb + c * 128 + o0);
            ulonglong2 wa = w2[0], wb = w2[1], wc = w2[2], wd = w2[3];
            ffma2(vpp[0][0], wa.x, g0p); ffma2(vpp[0][1], wa.x, g1p); ffma2(vpp[0][2], wa.x, g2p);
            ffma2(vpp[1][0], wa.y, g0p); ffma2(vpp[1][1], wa.y, g1p); ffma2(vpp[1][2], wa.y, g2p);
            ffma2(vpp[2][0], wb.x, g0p); ffma2(vpp[2][1], wb.x, g1p); ffma2(vpp[2][2], wb.x, g2p);
            ffma2(vpp[3][0], wb.y, g0p); ffma2(vpp[3][1], wb.y, g1p); ffma2(vpp[3][2], wb.y, g2p);
            ffma2(vpp[4][0], wc.x, g0p); ffma2(vpp[4][1], wc.x, g1p); ffma2(vpp[4][2], wc.x, g2p);
            ffma2(vpp[5][0], wc.y, g0p); ffma2(vpp[5][1], wc.y, g1p); ffma2(vpp[5][2], wc.y, g2p);
            ffma2(vpp[6][0], wd.x, g0p); ffma2(vpp[6][1], wd.x, g1p); ffma2(vpp[6][2], wd.x, g2p);
            ffma2(vpp[7][0], wd.y, g0p); ffma2(vpp[7][1], wd.y, g1p); ffma2(vpp[7][2], wd.y, g2p);
        }
#pragma unroll
        for (int jp = 0; jp < 8; jp++) {
            int ia = jp * 2, ib = jp * 2 + 1;
            float wra = sWr[o0 + ia], wrb = sWr[o0 + ib];
            float2 v0 = unpack2(vpp[jp][0]);
            float2 v1 = unpack2(vpp[jp][1]);
            float2 v2 = unpack2(vpp[jp][2]);
            vp[ia][0] = v0.x + wra * xr0;  vp[ib][0] = v0.y + wrb * xr0;
            vp[ia][1] = v1.x + wra * xr1;  vp[ib][1] = v1.y + wrb * xr1;
            vp[ia][2] = v2.x + wra * xr2;  vp[ib][2] = v2.y + wrb * xr2;
        }
    }
    __syncthreads();   // sA2 complete; sG/sWb dead -> sH/sAx aliases safe

    // ---- f1 GEMM (o-pair layout, dup-paired weights, 4-deep LDG prefetch) ----
    const int pr = tid & 63, sq = tid >> 6;
    {
        unsigned long long f0[4], f1a[4];
#pragma unroll
        for (int q = 0; q < 4; q++) { f0[q] = 0ull; f1a[q] = 0ull; }
        const ulonglong2* wp1 = (const ulonglong2*)d_Wf1P + pr;  // row stride 64 ull2
        ulonglong2 wbuf[4];
#pragma unroll
        for (int j = 0; j < 4; j++) wbuf[j] = __ldg(wp1 + j * 64);
        for (int cb = 0; cb < 384; cb += 4) {
#pragma unroll
            for (int j = 0; j < 4; j++) {
                ulonglong2 w = wbuf[j];
                wbuf[j] = __ldg(wp1 + (cb + 4 + j) * 64);
                const ulonglong2* av = (const ulonglong2*)(sA2 + (cb + j) * 32 + sq * 8);
                ulonglong2 a01 = av[0], a23 = av[1];
                ffma2(f0[0], a01.x, w.x); ffma2(f0[1], a01.y, w.x);
                ffma2(f0[2], a23.x, w.x); ffma2(f0[3], a23.y, w.x);
                ffma2(f1a[0], a01.x, w.y); ffma2(f1a[1], a01.y, w.y);
                ffma2(f1a[2], a23.x, w.y); ffma2(f1a[3], a23.y, w.y);
            }
        }
        float2 bb = __ldg((const float2*)bf1 + pr);
        float2* h0 = (float2*)(sH + (2 * pr) * 36 + sq * 8);
        float2* h1 = (float2*)(sH + (2 * pr + 1) * 36 + sq * 8);
#pragma unroll
        for (int q = 0; q < 4; q++) {
            float2 a = unpack2(f0[q]);
            float2 c = unpack2(f1a[q]);
            h0[q] = make_float2(fmaxf(a.x + bb.x, 0.f), fmaxf(a.y + bb.x, 0.f));
            h1[q] = make_float2(fmaxf(c.x + bb.y, 0.f), fmaxf(c.y + bb.y, 0.f));
        }
    }
    __syncthreads();   // f1 done: sA2 dead -> sVp alias safe

    // ---- spill vp to sVp [3][32][129] (conflict-free: bank = s + o mod 32) ----
    {
        float* vb = sVp + s * 129 + o0;
#pragma unroll
        for (int i = 0; i < 16; i++) {
            vb[i]        = vp[i][0];
            vb[i + 4128] = vp[i][1];
            vb[i + 8256] = vp[i][2];
        }
    }

    // ---- f2 GEMM (dup-paired weights, 4-deep LDG prefetch); logits -> sAx ----
    {
        unsigned long long f0[4], f1a[4];
#pragma unroll
        for (int q = 0; q < 4; q++) { f0[q] = 0ull; f1a[q] = 0ull; }
        const ulonglong2* wp2 = (const ulonglong2*)d_Wf2P + pr;
        ulonglong2 wbuf[4];
#pragma unroll
        for (int j = 0; j < 4; j++) wbuf[j] = __ldg(wp2 + j * 64);
        for (int cb = 0; cb < 128; cb += 4) {
#pragma unroll
            for (int j = 0; j < 4; j++) {
                ulonglong2 w = wbuf[j];
                wbuf[j] = __ldg(wp2 + (cb + 4 + j) * 64);
                const ulonglong2* hv = (const ulonglong2*)(sH + (cb + j) * 36 + sq * 8);
                ulonglong2 h01 = hv[0], h23 = hv[1];
                ffma2(f0[0], h01.x, w.x); ffma2(f0[1], h01.y, w.x);
                ffma2(f0[2], h23.x, w.x); ffma2(f0[3], h23.y, w.x);
                ffma2(f1a[0], h01.x, w.y); ffma2(f1a[1], h01.y, w.y);
                ffma2(f1a[2], h23.x, w.y); ffma2(f1a[3], h23.y, w.y);
            }
        }
        float2 bb = __ldg((const float2*)d_bf2s + pr);
        float2* x0 = (float2*)(sAx + (2 * pr) * 34 + sq * 8);
        float2* x1 = (float2*)(sAx + (2 * pr + 1) * 34 + sq * 8);
#pragma unroll
        for (int q = 0; q < 4; q++) {
            float2 a = unpack2(f0[q]);
            float2 c = unpack2(f1a[q]);
            x0[q] = make_float2(a.x + bb.x, a.y + bb.x);
            x1[q] = make_float2(c.x + bb.y, c.y + bb.y);
        }
    }
    __syncthreads();   // sAx + sVp visible to all

    // ---- softmax + weighted sum: thread-per-(o, s-half), single-shfl reductions ----
    {
        const int o = tid >> 1, h = tid & 1;
        const float2* ax2 = (const float2*)(sAx + o * 34 + h * 16);
        float x[16];
#pragma unroll
        for (int j = 0; j < 8; j++) {
            float2 v = ax2[j];
            x[2 * j] = v.x;
            x[2 * j + 1] = v.y;
        }
        float m = x[0];
#pragma unroll
        for (int j = 1; j < 16; j++) m = fmaxf(m, x[j]);
        m = fmaxf(m, __shfl_xor_sync(0xffffffffu, m, 1));
        float e[16];
        float den = 0.f;
#pragma unroll
        for (int j = 0; j < 16; j++) { e[j] = __expf(x[j] - m); den += e[j]; }
        den += __shfl_xor_sync(0xffffffffu, den, 1);
        float acc0 = 0.f, acc1 = 0.f, acc2 = 0.f;
        const float* vb = sVp + h * 16 * 129 + o;
#pragma unroll
        for (int j = 0; j < 16; j++) {
            float w = e[j];
            acc0 += w * vb[j * 129];
            acc1 += w * vb[j * 129 + 4128];
            acc2 += w * vb[j * 129 + 8256];
        }
        acc0 += __shfl_xor_sync(0xffffffffu, acc0, 1);
        acc1 += __shfl_xor_sync(0xffffffffu, acc1, 1);
        acc2 += __shfl_xor_sync(0xffffffffu, acc2, 1);
        if (h == 0) {
            float rden = 1.f / den;
            size_t base = (((size_t)b * 128 + o) * 3) * 1024 + n;
            out[base] = acc0 * rden;
            out[base + 1024] = acc1 * rden;
            out[base + 2048] = acc2 * rden;
        }
    }
}

extern "C" void kernel_launch(void* const* d_in, const int* in_sizes, int n_in,
                              void* d_out, int out_size) {
    (void)in_sizes; (void)n_in; (void)out_size;
    const float* gxyz = (const float*)d_in[0];
    const float* gfts = (const float*)d_in[1];
    const float* qxyz = (const float*)d_in[2];
    cudaFuncSetAttribute(main_kernel, cudaFuncAttributeMaxDynamicSharedMemorySize, SMEM_BYTES);
    dupT_kernel<<<8, 256>>>((const float*)d_in[11], (const float*)d_in[13]);
    prep1_kernel<<<128, 256>>>((const float*)d_in[3], (const float*)d_in[4]);
    prep2_kernel<<<128, 256>>>((const float*)d_in[5], (const float*)d_in[6],
                               (const float*)d_in[7], (const float*)d_in[8],
                               (const float*)d_in[9], (const float*)d_in[14]);
    main_kernel<<<NPTS, 256, SMEM_BYTES>>>(gxyz, gfts, qxyz,
                                           (const float*)d_in[10],
                                           (const float*)d_in[12],
                                           (float*)d_out);
}

// round 17
// speedup vs baseline: 1.2973x; 1.1164x over previous
#include <cuda_runtime.h>

#define NPTS 2048
// smem map (floats):
//   [0,6144)      sG   [64][3][32]        (aliased by sH [128][36]=4608 after v-pass)
//   [6144,14336)  sWb  [64][128] staged Wk then Wv  (aliased by sAx [128][34]=4352 after v-pass)
//   [14336,26720) sA2  [384][32]=12288    (first 2304 alias sZp; re-aliased by sVp [3][32][129] after f1)
//   [26720,28000) smalls: sXr 96 | sQ 384 | sWr 128 | sWstd 384 | sZ 288
#define SMEM_FLOATS 28000
#define SMEM_BYTES (SMEM_FLOATS * 4)

// -------- scratch (device globals: allocation-free) --------
__device__ float d_We21[128 * 64];
__device__ float d_WkT[64 * 128];
__device__ float d_WvT[64 * 128];
__device__ float d_WqT[64 * 128];
__device__ float d_Wr[128];
// compact transposed layouts: row c has 128 floats (one per o). +8 pad rows for prefetch overrun.
__device__ float d_Wf1T[392 * 128];
__device__ float d_Wf2T[136 * 128];
__device__ float d_bf2s[128];

// -------- packed f32x2 helpers (SASS FFMA2 path, PTX-only) --------
__device__ __forceinline__ void ffma2(unsigned long long& d,
                                      unsigned long long a,
                                      unsigned long long b) {
    asm("fma.rn.f32x2 %0, %1, %2, %0;" : "+l"(d) : "l"(a), "l"(b));
}
__device__ __forceinline__ unsigned long long pack2(float x) {
    unsigned long long r;
    asm("mov.b64 %0, {%1, %1};" : "=l"(r) : "f"(x));
    return r;
}
__device__ __forceinline__ float2 unpack2(unsigned long long v) {
    float2 f;
    asm("mov.b64 {%0, %1}, %2;" : "=f"(f.x), "=f"(f.y) : "l"(v));
    return f;
}

// ---------------- transT: coalesced weight transpose via smem tile ----------------
// blocks 0..5: Wf1 tiles (64 cc x 128 o); blocks 6..7: Wf2 tiles. Reads AND writes coalesced.
__global__ void transT_kernel(const float* __restrict__ Wf1, const float* __restrict__ Wf2) {
    __shared__ float tile[64 * 129];
    const float invS = 0.08838834764831845f;  // 1/sqrt(128)
    int blk = blockIdx.x, tid = threadIdx.x;
    if (blk < 6) {
        int cc0 = blk * 64;
        for (int idx = tid; idx < 8192; idx += 256) {
            int o = idx >> 6, cc = idx & 63;
            tile[cc * 129 + o] = Wf1[o * 384 + cc0 + cc];
        }
        __syncthreads();
        for (int idx = tid; idx < 8192; idx += 256) {
            int cc = idx >> 7, o = idx & 127;
            d_Wf1T[(cc0 + cc) * 128 + o] = tile[cc * 129 + o];
        }
        if (blk == 5)
            for (int idx = tid; idx < 1024; idx += 256) d_Wf1T[384 * 128 + idx] = 0.f;
    } else {
        int cc0 = (blk - 6) * 64;
        for (int idx = tid; idx < 8192; idx += 256) {
            int o = idx >> 6, cc = idx & 63;
            tile[cc * 129 + o] = Wf2[o * 128 + cc0 + cc] * invS;
        }
        __syncthreads();
        for (int idx = tid; idx < 8192; idx += 256) {
            int cc = idx >> 7, o = idx & 127;
            d_Wf2T[(cc0 + cc) * 128 + o] = tile[cc * 129 + o];
        }
        if (blk == 7)
            for (int idx = tid; idx < 1024; idx += 256) d_Wf2T[128 * 128 + idx] = 0.f;
    }
}

// ---------------- prep1: We21 = We2 @ We1 (128x64), 256-thread split-e ----------------
__global__ void prep1_kernel(const float* __restrict__ We1, const float* __restrict__ We2) {
    __shared__ float red[256];
    int t = blockIdx.x, tid = threadIdx.x;
    int c = tid & 63, eq = tid >> 6;
    float a = 0.f;
#pragma unroll 8
    for (int e = eq * 32; e < eq * 32 + 32; e++)
        a += We2[t * 128 + e] * We1[e * 64 + c];
    red[tid] = a;
    __syncthreads();
    if (tid < 64)
        d_We21[t * 64 + tid] = red[tid] + red[64 + tid] + red[128 + tid] + red[192 + tid];
}

// ---------------- prep2: fold q/k/v + Wr + bf2, 256-thread split-x ----------------
__global__ void prep2_kernel(const float* __restrict__ Wq, const float* __restrict__ Wk,
                             const float* __restrict__ Wv, const float* __restrict__ Wr1,
                             const float* __restrict__ Wr2, const float* __restrict__ bf2) {
    __shared__ float red[768];
    __shared__ float redr[64];
    const float invS = 0.08838834764831845f;  // 1/sqrt(128)
    int o = blockIdx.x, tid = threadIdx.x;
    int c = tid & 63, xq = tid >> 6;
    float ak = 0.f, av = 0.f, aq = 0.f;
#pragma unroll 8
    for (int x = xq * 32; x < xq * 32 + 32; x++) {
        float w21 = d_We21[x * 64 + c];
        ak += Wk[o * 128 + x] * w21;
        av += Wv[o * 128 + x] * w21;
        aq += Wq[o * 128 + x] * w21;
    }
    red[tid] = ak; red[256 + tid] = av; red[512 + tid] = aq;
    if (tid < 64) redr[tid] = Wr2[o * 64 + tid] * Wr1[tid];
    __syncthreads();
    if (tid < 64) {
        float sk = red[tid] + red[64 + tid] + red[128 + tid] + red[192 + tid];
        float sv = red[256 + tid] + red[320 + tid] + red[384 + tid] + red[448 + tid];
        float sq = red[512 + tid] + red[576 + tid] + red[640 + tid] + red[704 + tid];
        d_WkT[tid * 128 + o] = sk;
        d_WvT[tid * 128 + o] = sv;
        d_WqT[tid * 128 + o] = sq;
    } else if (tid == 64) {
        float r = 0.f;
#pragma unroll
        for (int i = 0; i < 64; i++) r += redr[i];
        d_Wr[o] = r;
        d_bf2s[o] = bf2[o] * invS;
    }
}

// ---------------- fully fused main kernel: one CTA per point, 2 CTAs/SM ----------------
__global__ __launch_bounds__(256, 2)
void main_kernel(const float* __restrict__ gxyz, const float* __restrict__ gfts,
                 const float* __restrict__ qxyz, const float* __restrict__ Wstd,
                 const float* __restrict__ bf1, float* __restrict__ out) {
    extern __shared__ float smf[];
    float* sG    = smf;             // [64][3][32]
    float* sWb   = smf + 6144;      // [64][128]  staged Wk, then Wv
    float* sA2   = smf + 14336;     // [384][32]
    float* sZp   = smf + 14336;     // [8][32][9] alias (dead before A2 written)
    float* sVp   = smf + 14336;     // [3][32][129] alias of sA2 (after f1)
    float* sH    = smf;             // [128][36]  alias sG (after v-pass)
    float* sAx   = smf + 6144;      // [128][34]  alias sWb (after v-pass)
    float* sXr   = smf + 26720;     // [3][32]
    float* sQ    = smf + 26816;     // [384]
    float* sWr   = smf + 27200;     // [128]
    float* sWstd = smf + 27328;     // [3][128]
    float* sZ    = smf + 27712;     // [9][32]

    const int p = blockIdx.x;
    const int b = p >> 10, n = p & 1023;
    const int tid = threadIdx.x;

    // ---- cooperative loads: G, Wk, smalls ----
    {
        const float4* gb4 = (const float4*)(gfts + (size_t)b * 6291456u + (size_t)n * 32u);
        for (int idx = tid; idx < 1536; idx += 256) {
            int c = idx / 24;
            int rem = idx - c * 24;
            int d = rem >> 3, s4 = rem & 7;
            ((float4*)sG)[idx] = gb4[c * 24576 + d * 8192 + s4];
        }
        for (int idx = tid; idx < 2048; idx += 256)
            ((float4*)sWb)[idx] = ((const float4*)d_WkT)[idx];
        for (int idx = tid; idx < 384; idx += 256)
            sWstd[idx] = Wstd[idx];
        if (tid < 128) sWr[tid] = d_Wr[tid];
        if (tid < 96) {
            int d = tid >> 5, s = tid & 31;
            sXr[tid] = gxyz[((size_t)p * 32 + s) * 3 + d] - qxyz[(size_t)p * 3 + d];
        }
    }
    __syncthreads();

    // ---- q inline: q[o][d] = sum_c WqT[c][o] * G[c][d][0] ----
    {
        int o = tid & 127;
        const float* wq = d_WqT + o;
        if (tid < 128) {
            float a0 = 0.f, a2 = 0.f;
#pragma unroll 8
            for (int c = 0; c < 64; c++) {
                float w = wq[c * 128];
                a0 += w * sG[c * 96];
                a2 += w * sG[c * 96 + 64];
            }
            sQ[o * 3 + 0] = a0;
            sQ[o * 3 + 2] = a2;
        } else {
            float a1 = 0.f;
#pragma unroll 8
            for (int c = 0; c < 64; c++)
                a1 += wq[c * 128] * sG[c * 96 + 32];
            sQ[o * 3 + 1] = a1;
        }
    }
    __syncthreads();

    const int s = tid & 31, r = tid >> 5, o0 = r << 4;
    const float xr0 = sXr[s], xr1 = sXr[32 + s], xr2 = sXr[64 + s];

    // ---- k-pass: k = WkT^T @ g via FFMA2 (weights from smem, broadcast) ----
    float at[16][3];
    {
        unsigned long long atp[8][3];
#pragma unroll
        for (int jp = 0; jp < 8; jp++)
#pragma unroll
            for (int d = 0; d < 3; d++) atp[jp][d] = 0ull;
#pragma unroll 2
        for (int c = 0; c < 64; c++) {
            unsigned long long g0p = pack2(sG[c * 96 + s]);
            unsigned long long g1p = pack2(sG[c * 96 + 32 + s]);
            unsigned long long g2p = pack2(sG[c * 96 + 64 + s]);
            const ulonglong2* w2 = (const ulonglong2*)(sWb + c * 128 + o0);
            ulonglong2 wa = w2[0], wb = w2[1], wc = w2[2], wd = w2[3];
            ffma2(atp[0][0], wa.x, g0p); ffma2(atp[0][1], wa.x, g1p); ffma2(atp[0][2], wa.x, g2p);
            ffma2(atp[1][0], wa.y, g0p); ffma2(atp[1][1], wa.y, g1p); ffma2(atp[1][2], wa.y, g2p);
            ffma2(atp[2][0], wb.x, g0p); ffma2(atp[2][1], wb.x, g1p); ffma2(atp[2][2], wb.x, g2p);
            ffma2(atp[3][0], wb.y, g0p); ffma2(atp[3][1], wb.y, g1p); ffma2(atp[3][2], wb.y, g2p);
            ffma2(atp[4][0], wc.x, g0p); ffma2(atp[4][1], wc.x, g1p); ffma2(atp[4][2], wc.x, g2p);
            ffma2(atp[5][0], wc.y, g0p); ffma2(atp[5][1], wc.y, g1p); ffma2(atp[5][2], wc.y, g2p);
            ffma2(atp[6][0], wd.x, g0p); ffma2(atp[6][1], wd.x, g1p); ffma2(atp[6][2], wd.x, g2p);
            ffma2(atp[7][0], wd.y, g0p); ffma2(atp[7][1], wd.y, g1p); ffma2(atp[7][2], wd.y, g2p);
        }
        // attn = q - k + pr
#pragma unroll
        for (int jp = 0; jp < 8; jp++) {
            int ia = jp * 2, ib = jp * 2 + 1;
            float wra = sWr[o0 + ia], wrb = sWr[o0 + ib];
            float2 k0 = unpack2(atp[jp][0]);
            float2 k1 = unpack2(atp[jp][1]);
            float2 k2 = unpack2(atp[jp][2]);
            at[ia][0] = sQ[(o0 + ia) * 3 + 0] - k0.x + wra * xr0;
            at[ib][0] = sQ[(o0 + ib) * 3 + 0] - k0.y + wrb * xr0;
            at[ia][1] = sQ[(o0 + ia) * 3 + 1] - k1.x + wra * xr1;
            at[ib][1] = sQ[(o0 + ib) * 3 + 1] - k1.y + wrb * xr1;
            at[ia][2] = sQ[(o0 + ia) * 3 + 2] - k2.x + wra * xr2;
            at[ib][2] = sQ[(o0 + ib) * 3 + 2] - k2.y + wrb * xr2;
        }
    }

    // ---- z0 partials (into sZp, alias of sA2 — A2 not yet written) ----
    {
        float pz[9];
#pragma unroll
        for (int jk = 0; jk < 9; jk++) pz[jk] = 0.f;
#pragma unroll
        for (int i = 0; i < 16; i++) {
            float w0 = sWstd[o0 + i];
            float w1 = sWstd[128 + o0 + i];
            float w2 = sWstd[256 + o0 + i];
#pragma unroll
            for (int k = 0; k < 3; k++) {
                float a = at[i][k];
                pz[0 * 3 + k] += w0 * a;
                pz[1 * 3 + k] += w1 * a;
                pz[2 * 3 + k] += w2 * a;
            }
        }
#pragma unroll
        for (int jk = 0; jk < 9; jk++) sZp[(r * 32 + s) * 9 + jk] = pz[jk];
    }
    __syncthreads();   // k-pass reads of sWb complete; sZp visible

    // ---- overlap: warp 0 reduces z0; everyone restages Wv into sWb ----
    for (int idx = tid; idx < 2048; idx += 256)
        ((float4*)sWb)[idx] = ((const float4*)d_WvT)[idx];
    if (r == 0) {
#pragma unroll
        for (int jk = 0; jk < 9; jk++) {
            float v = 0.f;
#pragma unroll
            for (int rr = 0; rr < 8; rr++) v += sZp[(rr * 32 + s) * 9 + jk];
            sZ[jk * 32 + s] = v;
        }
    }
    __syncthreads();

    // ---- attn2 = attn @ z0 -> sA2 (clobbers sZp, now dead) ----
    {
        float z[9];
#pragma unroll
        for (int jk = 0; jk < 9; jk++) z[jk] = sZ[jk * 32 + s];
#pragma unroll
        for (int i = 0; i < 16; i++) {
#pragma unroll
            for (int k = 0; k < 3; k++) {
                float a2 = at[i][0] * z[0 * 3 + k] + at[i][1] * z[1 * 3 + k] + at[i][2] * z[2 * 3 + k];
                sA2[((o0 + i) * 3 + k) * 32 + s] = a2;
            }
        }
    }

    // ---- v-pass: v = WvT^T @ g ; vp = v + pr stays in REGISTERS (until after f1) ----
    float vp[16][3];
    {
        unsigned long long vpp[8][3];
#pragma unroll
        for (int jp = 0; jp < 8; jp++)
#pragma unroll
            for (int d = 0; d < 3; d++) vpp[jp][d] = 0ull;
#pragma unroll 2
        for (int c = 0; c < 64; c++) {
            unsigned long long g0p = pack2(sG[c * 96 + s]);
            unsigned long long g1p = pack2(sG[c * 96 + 32 + s]);
            unsigned long long g2p = pack2(sG[c * 96 + 64 + s]);
            const ulonglong2* w2 = (const ulonglong2*)(sWb + c * 128 + o0);
            ulonglong2 wa = w2[0], wb = w2[1], wc = w2[2], wd = w2[3];
            ffma2(vpp[0][0], wa.x, g0p); ffma2(vpp[0][1], wa.x, g1p); ffma2(vpp[0][2], wa.x, g2p);
            ffma2(vpp[1][0], wa.y, g0p); ffma2(vpp[1][1], wa.y, g1p); ffma2(vpp[1][2], wa.y, g2p);
            ffma2(vpp[2][0], wb.x, g0p); ffma2(vpp[2][1], wb.x, g1p); ffma2(vpp[2][2], wb.x, g2p);
            ffma2(vpp[3][0], wb.y, g0p); ffma2(vpp[3][1], wb.y, g1p); ffma2(vpp[3][2], wb.y, g2p);
            ffma2(vpp[4][0], wc.x, g0p); ffma2(vpp[4][1], wc.x, g1p); ffma2(vpp[4][2], wc.x, g2p);
            ffma2(vpp[5][0], wc.y, g0p); ffma2(vpp[5][1], wc.y, g1p); ffma2(vpp[5][2], wc.y, g2p);
            ffma2(vpp[6][0], wd.x, g0p); ffma2(vpp[6][1], wd.x, g1p); ffma2(vpp[6][2], wd.x, g2p);
            ffma2(vpp[7][0], wd.y, g0p); ffma2(vpp[7][1], wd.y, g1p); ffma2(vpp[7][2], wd.y, g2p);
        }
#pragma unroll
        for (int jp = 0; jp < 8; jp++) {
            int ia = jp * 2, ib = jp * 2 + 1;
            float wra = sWr[o0 + ia], wrb = sWr[o0 + ib];
            float2 v0 = unpack2(vpp[jp][0]);
            float2 v1 = unpack2(vpp[jp][1]);
            float2 v2 = unpack2(vpp[jp][2]);
            vp[ia][0] = v0.x + wra * xr0;  vp[ib][0] = v0.y + wrb * xr0;
            vp[ia][1] = v1.x + wra * xr1;  vp[ib][1] = v1.y + wrb * xr1;
            vp[ia][2] = v2.x + wra * xr2;  vp[ib][2] = v2.y + wrb * xr2;
        }
    }
    __syncthreads();   // sA2 complete; sG/sWb dead -> sH/sAx aliases safe

    // ---- f1 GEMM (o-pair layout, compact float2 weights + pack2, 4-deep LDG prefetch) ----
    const int pr = tid & 63, sq = tid >> 6;
    {
        unsigned long long f0[4], f1a[4];
#pragma unroll
        for (int q = 0; q < 4; q++) { f0[q] = 0ull; f1a[q] = 0ull; }
        const float2* wp1 = (const float2*)d_Wf1T + pr;  // row stride 64 float2
        float2 wbuf[4];
#pragma unroll
        for (int j = 0; j < 4; j++) wbuf[j] = __ldg(wp1 + j * 64);
        for (int cb = 0; cb < 384; cb += 4) {
#pragma unroll
            for (int j = 0; j < 4; j++) {
                float2 w = wbuf[j];
                wbuf[j] = __ldg(wp1 + (cb + 4 + j) * 64);
                unsigned long long wx = pack2(w.x);
                unsigned long long wy = pack2(w.y);
                const ulonglong2* av = (const ulonglong2*)(sA2 + (cb + j) * 32 + sq * 8);
                ulonglong2 a01 = av[0], a23 = av[1];
                ffma2(f0[0], a01.x, wx); ffma2(f0[1], a01.y, wx);
                ffma2(f0[2], a23.x, wx); ffma2(f0[3], a23.y, wx);
                ffma2(f1a[0], a01.x, wy); ffma2(f1a[1], a01.y, wy);
                ffma2(f1a[2], a23.x, wy); ffma2(f1a[3], a23.y, wy);
            }
        }
        float2 bb = __ldg((const float2*)bf1 + pr);
        float2* h0 = (float2*)(sH + (2 * pr) * 36 + sq * 8);
        float2* h1 = (float2*)(sH + (2 * pr + 1) * 36 + sq * 8);
#pragma unroll
        for (int q = 0; q < 4; q++) {
            float2 a = unpack2(f0[q]);
            float2 c = unpack2(f1a[q]);
            h0[q] = make_float2(fmaxf(a.x + bb.x, 0.f), fmaxf(a.y + bb.x, 0.f));
            h1[q] = make_float2(fmaxf(c.x + bb.y, 0.f), fmaxf(c.y + bb.y, 0.f));
        }
    }
    __syncthreads();   // f1 done: sA2 dead -> sVp alias safe

    // ---- spill vp to sVp [3][32][129] (conflict-free: bank = s + o mod 32) ----
    {
        float* vb = sVp + s * 129 + o0;
#pragma unroll
        for (int i = 0; i < 16; i++) {
            vb[i]        = vp[i][0];
            vb[i + 4128] = vp[i][1];
            vb[i + 8256] = vp[i][2];
        }
    }

    // ---- f2 GEMM (compact float2 weights + pack2, 4-deep LDG prefetch); logits -> sAx ----
    {
        unsigned long long f0[4], f1a[4];
#pragma unroll
        for (int q = 0; q < 4; q++) { f0[q] = 0ull; f1a[q] = 0ull; }
        const float2* wp2 = (const float2*)d_Wf2T + pr;
        float2 wbuf[4];
#pragma unroll
        for (int j = 0; j < 4; j++) wbuf[j] = __ldg(wp2 + j * 64);
        for (int cb = 0; cb < 128; cb += 4) {
#pragma unroll
            for (int j = 0; j < 4; j++) {
                float2 w = wbuf[j];
                wbuf[j] = __ldg(wp2 + (cb + 4 + j) * 64);
                unsigned long long wx = pack2(w.x);
                unsigned long long wy = pack2(w.y);
                const ulonglong2* hv = (const ulonglong2*)(sH + (cb + j) * 36 + sq * 8);
                ulonglong2 h01 = hv[0], h23 = hv[1];
                ffma2(f0[0], h01.x, wx); ffma2(f0[1], h01.y, wx);
                ffma2(f0[2], h23.x, wx); ffma2(f0[3], h23.y, wx);
                ffma2(f1a[0], h01.x, wy); ffma2(f1a[1], h01.y, wy);
                ffma2(f1a[2], h23.x, wy); ffma2(f1a[3], h23.y, wy);
            }
        }
        float2 bb = __ldg((const float2*)d_bf2s + pr);
        float2* x0 = (float2*)(sAx + (2 * pr) * 34 + sq * 8);
        float2* x1 = (float2*)(sAx + (2 * pr + 1) * 34 + sq * 8);
#pragma unroll
        for (int q = 0; q < 4; q++) {
            float2 a = unpack2(f0[q]);
            float2 c = unpack2(f1a[q]);
            x0[q] = make_float2(a.x + bb.x, a.y + bb.x);
            x1[q] = make_float2(c.x + bb.y, c.y + bb.y);
        }
    }
    __syncthreads();   // sAx + sVp visible to all

    // ---- softmax + weighted sum: thread-per-(o, s-half), single-shfl reductions ----
    {
        const int o = tid >> 1, h = tid & 1;
        const float2* ax2 = (const float2*)(sAx + o * 34 + h * 16);
        float x[16];
#pragma unroll
        for (int j = 0; j < 8; j++) {
            float2 v = ax2[j];
            x[2 * j] = v.x;
            x[2 * j + 1] = v.y;
        }
        float m = x[0];
#pragma unroll
        for (int j = 1; j < 16; j++) m = fmaxf(m, x[j]);
        m = fmaxf(m, __shfl_xor_sync(0xffffffffu, m, 1));
        float e[16];
        float den = 0.f;
#pragma unroll
        for (int j = 0; j < 16; j++) { e[j] = __expf(x[j] - m); den += e[j]; }
        den += __shfl_xor_sync(0xffffffffu, den, 1);
        float acc0 = 0.f, acc1 = 0.f, acc2 = 0.f;
        const float* vb = sVp + h * 16 * 129 + o;
#pragma unroll
        for (int j = 0; j < 16; j++) {
            float w = e[j];
            acc0 += w * vb[j * 129];
            acc1 += w * vb[j * 129 + 4128];
            acc2 += w * vb[j * 129 + 8256];
        }
        acc0 += __shfl_xor_sync(0xffffffffu, acc0, 1);
        acc1 += __shfl_xor_sync(0xffffffffu, acc1, 1);
        acc2 += __shfl_xor_sync(0xffffffffu, acc2, 1);
        if (h == 0) {
            float rden = 1.f / den;
            size_t base = (((size_t)b * 128 + o) * 3) * 1024 + n;
            out[base] = acc0 * rden;
            out[base + 1024] = acc1 * rden;
            out[base + 2048] = acc2 * rden;
        }
    }
}

extern "C" void kernel_launch(void* const* d_in, const int* in_sizes, int n_in,
                              void* d_out, int out_size) {
    (void)in_sizes; (void)n_in; (void)out_size;
    const float* gxyz = (const float*)d_in[0];
    const float* gfts = (const float*)d_in[1];
    const float* qxyz = (const float*)d_in[2];
    cudaFuncSetAttribute(main_kernel, cudaFuncAttributeMaxDynamicSharedMemorySize, SMEM_BYTES);
    transT_kernel<<<8, 256>>>((const float*)d_in[11], (const float*)d_in[13]);
    prep1_kernel<<<128, 256>>>((const float*)d_in[3], (const float*)d_in[4]);
    prep2_kernel<<<128, 256>>>((const float*)d_in[5], (const float*)d_in[6],
                               (const float*)d_in[7], (const float*)d_in[8],
                               (const float*)d_in[9], (const float*)d_in[14]);
    main_kernel<<<NPTS, 256, SMEM_BYTES>>>(gxyz, gfts, qxyz,
                                           (const float*)d_in[10],
                                           (const float*)d_in[12],
                                           (float*)d_out);
}